// round 1
// baseline (speedup 1.0000x reference)
#include <cuda_runtime.h>
#include <math.h>

#define B 64
#define S 512
#define D 768
#define W 256
#define KX 1536   // 2*D router input
#define H 256     // router hidden
#define L 7       // num labels
#define TW 64     // words per router block
#define KT 32     // k-tile

// Word-state scratch: [B*W rows][0:768 = hing mean | 768:1536 = rob mean]
__device__ float g_x[(size_t)B * W * KX];

// ---------------------------------------------------------------------------
// Kernel A: segment-mean align. word_ids are sorted per row, so word w's
// subtokens are a contiguous range found via two binary searches.
// One block per (b, w). 256 threads cover D=768 (3 elems/thread).
// ---------------------------------------------------------------------------
__global__ __launch_bounds__(256) void align_kernel(
    const float* __restrict__ hing, const float* __restrict__ rob,
    const int* __restrict__ hids, const int* __restrict__ rids)
{
    int row = blockIdx.x;          // b*W + w
    int b = row >> 8;
    int w = row & (W - 1);

    #pragma unroll
    for (int srci = 0; srci < 2; srci++) {
        const int* ids = (srci ? rids : hids) + b * S;
        const float* src = srci ? rob : hing;
        float* dst = g_x + (size_t)row * KX + srci * D;

        // lower_bound(w)
        int l = 0, r = S;
        while (l < r) { int m = (l + r) >> 1; if (__ldg(ids + m) < w) l = m + 1; else r = m; }
        int lo = l;
        // lower_bound(w+1) == upper_bound(w)
        r = S;
        while (l < r) { int m = (l + r) >> 1; if (__ldg(ids + m) <= w) l = m + 1; else r = m; }
        int hi = l;

        float inv = (hi > lo) ? 1.0f / (float)(hi - lo) : 0.0f;
        const float* base = src + (size_t)b * S * D;
        for (int d = threadIdx.x; d < D; d += 256) {
            float acc = 0.0f;
            for (int s = lo; s < hi; s++) acc += __ldg(base + (size_t)s * D + d);
            dst[d] = acc * inv;
        }
    }
}

// ---------------------------------------------------------------------------
// Kernel B: fused router MLP + blend + head + l2.
// Block = TW=64 words. GEMM1: C[64x256] = X[64x1536] * W1[1536x256],
// register-tiled 8x8 per thread (256 threads). hdn stays in registers;
// alpha via warp reduce; epilogue re-reads word states from g_x.
// ---------------------------------------------------------------------------
__global__ __launch_bounds__(256, 2) void router_kernel(
    const float* __restrict__ w1, const float* __restrict__ b1,
    const float* __restrict__ w2, const float* __restrict__ b2p,
    const float* __restrict__ headw, const float* __restrict__ headb,
    float* __restrict__ out)
{
    __shared__ float Xs[TW][KT];     // 8 KB
    __shared__ float Ws[KT][H];      // 32 KB
    __shared__ float s_b1[H];
    __shared__ float s_w2[H];
    __shared__ float s_alpha[TW];

    int tid = threadIdx.x;
    int r0 = blockIdx.x * TW;
    s_b1[tid] = b1[tid];
    s_w2[tid] = w2[tid];

    int tx = tid & 31;   // column lane (cols tx + 32*j)
    int ty = tid >> 5;   // warp id   (rows ty + 8*i)

    float acc[8][8];
    #pragma unroll
    for (int i = 0; i < 8; i++)
        #pragma unroll
        for (int j = 0; j < 8; j++) acc[i][j] = 0.0f;

    for (int kk = 0; kk < KX; kk += KT) {
        __syncthreads();
        #pragma unroll
        for (int i = 0; i < 8; i++) {
            int idx = i * 256 + tid;                 // 0..2047
            int rr = idx >> 5, cc = idx & 31;
            Xs[rr][cc] = g_x[(size_t)(r0 + rr) * KX + kk + cc];
        }
        #pragma unroll
        for (int i = 0; i < KT; i++) {
            Ws[i][tid] = __ldg(w1 + (size_t)(kk + i) * H + tid);
        }
        __syncthreads();

        #pragma unroll
        for (int k = 0; k < KT; k++) {
            float a[8], bb[8];
            #pragma unroll
            for (int i = 0; i < 8; i++) a[i] = Xs[ty + 8 * i][k];
            #pragma unroll
            for (int j = 0; j < 8; j++) bb[j] = Ws[k][tx + 32 * j];
            #pragma unroll
            for (int i = 0; i < 8; i++)
                #pragma unroll
                for (int j = 0; j < 8; j++)
                    acc[i][j] = fmaf(a[i], bb[j], acc[i][j]);
        }
    }

    // alpha = sigmoid(relu(hdn + b1) . w2 + b2), reduced across the warp
    float b2 = __ldg(b2p);
    #pragma unroll
    for (int i = 0; i < 8; i++) {
        float part = 0.0f;
        #pragma unroll
        for (int j = 0; j < 8; j++) {
            int c = tx + 32 * j;
            float h = acc[i][j] + s_b1[c];
            h = h > 0.0f ? h : 0.0f;
            part = fmaf(h, s_w2[c], part);
        }
        #pragma unroll
        for (int o = 16; o > 0; o >>= 1)
            part += __shfl_xor_sync(0xffffffffu, part, o);
        if (tx == 0) {
            float z = part + b2;
            s_alpha[ty + 8 * i] = 1.0f / (1.0f + expf(-z));
        }
    }
    __syncthreads();

    // Epilogue: warp ty owns words [ty*8, ty*8+8)
    float* out_logits = out;
    float* out_alpha  = out + (size_t)B * W * L;
    float* out_l2     = out_alpha + (size_t)B * W;

    #pragma unroll 1
    for (int wi = 0; wi < 8; wi++) {
        int li = ty * 8 + wi;
        size_t row = (size_t)(r0 + li);
        float al = s_alpha[li];
        float oma = 1.0f - al;
        const float* xh = g_x + row * KX;
        const float* xr = xh + D;

        float lg[L];
        #pragma unroll
        for (int l = 0; l < L; l++) lg[l] = 0.0f;
        float l2 = 0.0f;

        for (int d = tx; d < D; d += 32) {
            float hh = __ldg(xh + d);
            float hr = __ldg(xr + d);
            float bl = al * hh + oma * hr;
            float df = hh - hr;
            l2 = fmaf(df, df, l2);
            #pragma unroll
            for (int l = 0; l < L; l++)
                lg[l] = fmaf(bl, __ldg(headw + (size_t)d * L + l), lg[l]);
        }
        #pragma unroll
        for (int o = 16; o > 0; o >>= 1) {
            #pragma unroll
            for (int l = 0; l < L; l++)
                lg[l] += __shfl_xor_sync(0xffffffffu, lg[l], o);
            l2 += __shfl_xor_sync(0xffffffffu, l2, o);
        }
        if (tx == 0) {
            #pragma unroll
            for (int l = 0; l < L; l++)
                out_logits[row * L + l] = lg[l] + __ldg(headb + l);
            out_alpha[row] = al;
            out_l2[row] = sqrtf(l2);
        }
    }
}

extern "C" void kernel_launch(void* const* d_in, const int* in_sizes, int n_in,
                              void* d_out, int out_size)
{
    const float* hing = (const float*)d_in[0];
    const float* rob  = (const float*)d_in[1];
    const int*   hids = (const int*)d_in[2];
    const int*   rids = (const int*)d_in[3];
    // d_in[4] = num_words (unused by the reference outputs)
    const float* w1 = (const float*)d_in[5];
    const float* b1 = (const float*)d_in[6];
    const float* w2 = (const float*)d_in[7];
    const float* b2 = (const float*)d_in[8];
    const float* hw = (const float*)d_in[9];
    const float* hb = (const float*)d_in[10];
    float* out = (float*)d_out;

    align_kernel<<<B * W, 256>>>(hing, rob, hids, rids);
    router_kernel<<<(B * W) / TW, 256>>>(w1, b1, w2, b2, hw, hb, out);
}

// round 2
// speedup vs baseline: 1.1574x; 1.1574x over previous
#include <cuda_runtime.h>
#include <math.h>

#define B 64
#define S 512
#define D 768
#define W 256
#define KX 1536   // 2*D router input
#define H 256     // router hidden
#define L 7       // num labels
#define TW 64     // words per router block
#define KT 32     // k-tile

// Word-state scratch: [B*W rows][0:768 = hing mean | 768:1536 = rob mean]
__device__ float g_x[(size_t)B * W * KX];

__device__ __forceinline__ unsigned long long pack2(float lo, float hi) {
    unsigned long long r;
    asm("mov.b64 %0, {%1, %2};" : "=l"(r) : "f"(lo), "f"(hi));
    return r;
}
__device__ __forceinline__ void unpack2(unsigned long long v, float& lo, float& hi) {
    asm("mov.b64 {%0, %1}, %2;" : "=f"(lo), "=f"(hi) : "l"(v));
}
__device__ __forceinline__ void ffma2(unsigned long long& acc,
                                      unsigned long long a,
                                      unsigned long long b) {
    asm("fma.rn.f32x2 %0, %1, %2, %0;" : "+l"(acc) : "l"(a), "l"(b));
}

// ---------------------------------------------------------------------------
// Kernel A: segment-mean align. word_ids sorted per row -> contiguous slices
// found via binary search. One WARP per (row, source). float4 everywhere.
// grid = B*W*2/8 = 4096 blocks of 256 threads (8 warps).
// ---------------------------------------------------------------------------
__global__ __launch_bounds__(256) void align_kernel(
    const float* __restrict__ hing, const float* __restrict__ rob,
    const int* __restrict__ hids, const int* __restrict__ rids)
{
    int unit = blockIdx.x * 8 + (threadIdx.x >> 5);  // 0 .. B*W*2-1
    int lane = threadIdx.x & 31;
    int srci = unit & 1;
    int row  = unit >> 1;            // b*W + w
    int b = row >> 8;
    int w = row & (W - 1);

    const int* ids = (srci ? rids : hids) + b * S;
    const float* src = srci ? rob : hing;

    // lower_bound(w) and lower_bound(w+1), all lanes redundantly (divergence-free)
    int l = 0, r = S;
    while (l < r) { int m = (l + r) >> 1; if (ids[m] < w) l = m + 1; else r = m; }
    int lo = l;
    r = S;
    while (l < r) { int m = (l + r) >> 1; if (ids[m] <= w) l = m + 1; else r = m; }
    int hi = l;

    float inv = (hi > lo) ? 1.0f / (float)(hi - lo) : 0.0f;
    const float4* base = (const float4*)(src + (size_t)b * S * D);
    float4* dst = (float4*)(g_x + (size_t)row * KX + srci * D);

    const int D4 = D / 4;   // 192
    #pragma unroll 1
    for (int d = lane; d < D4; d += 32) {
        float ax = 0.f, ay = 0.f, az = 0.f, aw = 0.f;
        for (int s = lo; s < hi; s++) {
            float4 v = base[(size_t)s * D4 + d];
            ax += v.x; ay += v.y; az += v.z; aw += v.w;
        }
        float4 o; o.x = ax * inv; o.y = ay * inv; o.z = az * inv; o.w = aw * inv;
        dst[d] = o;
    }
}

// ---------------------------------------------------------------------------
// Kernel B: fused router MLP + blend + head + l2, packed f32x2 FFMA.
// Block = TW=64 words, 256 threads. Warp ty owns rows [ty*8, ty*8+8),
// lane tx owns cols [tx*8, tx*8+8) as 4 f32x2 pairs.
// Per k-step: 8 scalar broadcast LDS (a) + 2 x ld.shared.v2.u64 (b)
//             + 8 mov.b64 packs + 32 fma.rn.f32x2.
// ---------------------------------------------------------------------------
__global__ __launch_bounds__(256, 2) void router_kernel(
    const float* __restrict__ w1, const float* __restrict__ b1,
    const float* __restrict__ w2, const float* __restrict__ b2p,
    const float* __restrict__ headw, const float* __restrict__ headb,
    float* __restrict__ out)
{
    __shared__ float Xs[TW][KT];     // 8 KB
    __shared__ float Ws[KT][H];      // 32 KB
    __shared__ float s_b1[H];
    __shared__ float s_w2[H];
    __shared__ float s_alpha[TW];

    int tid = threadIdx.x;
    int r0 = blockIdx.x * TW;
    s_b1[tid] = b1[tid];
    s_w2[tid] = w2[tid];

    int tx = tid & 31;   // lane: cols tx*8 .. tx*8+7
    int ty = tid >> 5;   // warp: rows ty*8 .. ty*8+7

    unsigned long long acc[8][4];
    #pragma unroll
    for (int i = 0; i < 8; i++)
        #pragma unroll
        for (int p = 0; p < 4; p++) acc[i][p] = 0ULL;

    for (int kk = 0; kk < KX; kk += KT) {
        __syncthreads();
        // Xs tile: 64 rows x 32 k, float4 loads (coalesced)
        #pragma unroll
        for (int t = 0; t < 2; t++) {
            int idx = t * 256 + tid;           // 0..511 float4 slots
            int rr = idx >> 3;
            int c4 = (idx & 7) * 4;
            *(float4*)&Xs[rr][c4] =
                *(const float4*)&g_x[(size_t)(r0 + rr) * KX + kk + c4];
        }
        // Ws tile: 32 k x 256 cols, float4 loads (coalesced)
        #pragma unroll
        for (int t = 0; t < 8; t++) {
            int idx = t * 256 + tid;           // 0..2047 float4 slots
            ((float4*)Ws)[idx] = ((const float4*)(w1 + (size_t)kk * H))[idx];
        }
        __syncthreads();

        #pragma unroll
        for (int k = 0; k < KT; k++) {
            const ulonglong2* wp = (const ulonglong2*)&Ws[k][tx * 8];
            ulonglong2 w01 = wp[0];
            ulonglong2 w23 = wp[1];
            #pragma unroll
            for (int i = 0; i < 8; i++) {
                float a = Xs[ty * 8 + i][k];            // warp-uniform broadcast
                unsigned long long a2 = pack2(a, a);
                ffma2(acc[i][0], a2, w01.x);
                ffma2(acc[i][1], a2, w01.y);
                ffma2(acc[i][2], a2, w23.x);
                ffma2(acc[i][3], a2, w23.y);
            }
        }
    }

    // alpha = sigmoid(relu(hdn + b1) . w2 + b2), reduced across the warp
    float b2 = *b2p;
    #pragma unroll
    for (int i = 0; i < 8; i++) {
        float part = 0.0f;
        #pragma unroll
        for (int p = 0; p < 4; p++) {
            float h0, h1;
            unpack2(acc[i][p], h0, h1);
            int c = tx * 8 + p * 2;
            h0 += s_b1[c];     h1 += s_b1[c + 1];
            h0 = h0 > 0.f ? h0 : 0.f;
            h1 = h1 > 0.f ? h1 : 0.f;
            part = fmaf(h0, s_w2[c], part);
            part = fmaf(h1, s_w2[c + 1], part);
        }
        #pragma unroll
        for (int o = 16; o > 0; o >>= 1)
            part += __shfl_xor_sync(0xffffffffu, part, o);
        if (tx == 0) {
            float z = part + b2;
            s_alpha[ty * 8 + i] = 1.0f / (1.0f + expf(-z));
        }
    }
    __syncthreads();

    // Epilogue: warp ty owns words [ty*8, ty*8+8)
    float* out_logits = out;
    float* out_alpha  = out + (size_t)B * W * L;
    float* out_l2     = out_alpha + (size_t)B * W;

    #pragma unroll 1
    for (int wi = 0; wi < 8; wi++) {
        int li = ty * 8 + wi;
        size_t row = (size_t)(r0 + li);
        float al = s_alpha[li];
        float oma = 1.0f - al;
        const float* xh = g_x + row * KX;
        const float* xr = xh + D;

        float lg[L];
        #pragma unroll
        for (int l = 0; l < L; l++) lg[l] = 0.0f;
        float l2 = 0.0f;

        #pragma unroll 1
        for (int d = tx; d < D; d += 32) {
            float hh = xh[d];
            float hr = xr[d];
            float bl = al * hh + oma * hr;
            float df = hh - hr;
            l2 = fmaf(df, df, l2);
            #pragma unroll
            for (int l = 0; l < L; l++)
                lg[l] = fmaf(bl, headw[(size_t)d * L + l], lg[l]);
        }
        #pragma unroll
        for (int o = 16; o > 0; o >>= 1) {
            #pragma unroll
            for (int l = 0; l < L; l++)
                lg[l] += __shfl_xor_sync(0xffffffffu, lg[l], o);
            l2 += __shfl_xor_sync(0xffffffffu, l2, o);
        }
        if (tx == 0) {
            #pragma unroll
            for (int l = 0; l < L; l++)
                out_logits[row * L + l] = lg[l] + headb[l];
            out_alpha[row] = al;
            out_l2[row] = sqrtf(l2);
        }
    }
}

extern "C" void kernel_launch(void* const* d_in, const int* in_sizes, int n_in,
                              void* d_out, int out_size)
{
    const float* hing = (const float*)d_in[0];
    const float* rob  = (const float*)d_in[1];
    const int*   hids = (const int*)d_in[2];
    const int*   rids = (const int*)d_in[3];
    // d_in[4] = num_words (unused by the reference outputs)
    const float* w1 = (const float*)d_in[5];
    const float* b1 = (const float*)d_in[6];
    const float* w2 = (const float*)d_in[7];
    const float* b2 = (const float*)d_in[8];
    const float* hw = (const float*)d_in[9];
    const float* hb = (const float*)d_in[10];
    float* out = (float*)d_out;

    align_kernel<<<(B * W * 2) / 8, 256>>>(hing, rob, hids, rids);
    router_kernel<<<(B * W) / TW, 256>>>(w1, b1, w2, b2, hw, hb, out);
}

// round 4
// speedup vs baseline: 2.3450x; 2.0261x over previous
#include <cuda_runtime.h>
#include <cuda_bf16.h>
#include <math.h>
#include <stdint.h>

#define BATCH 64
#define S 512
#define D 768
#define W 256
#define KX 1536     // 2*D router input
#define H 256       // router hidden (= GEMM N)
#define L 7
#define ROWS (BATCH * W)   // 16384
#define CTA_M 64
#define KT2 64             // K-tile (bf16 elems) = 128 bytes = one SW128 row
#define NITER (KX / KT2)   // 24

// stage layout (bytes): Ah 8K | Al 8K | Bh 32K | Bl 32K
#define OFF_AH 0u
#define OFF_AL 8192u
#define OFF_BH 16384u
#define OFF_BL 49152u
#define STAGE_BYTES 81920u
#define OFF_TILES 4096u
#define SMEM_TOTAL (OFF_TILES + 2 * STAGE_BYTES)   // 167936

// bf16 split operands
__device__ __align__(16) __nv_bfloat16 g_xh[(size_t)ROWS * KX];
__device__ __align__(16) __nv_bfloat16 g_xl[(size_t)ROWS * KX];
__device__ __align__(16) __nv_bfloat16 g_w1h[(size_t)H * KX];   // [n][k]
__device__ __align__(16) __nv_bfloat16 g_w1l[(size_t)H * KX];

__device__ __forceinline__ uint32_t smem_u32(const void* p) {
    uint32_t a;
    asm("{ .reg .u64 t; cvta.to.shared.u64 t, %1; cvt.u32.u64 %0, t; }"
        : "=r"(a) : "l"(p));
    return a;
}
#define SWZ(x) ((x) ^ (((x) >> 3) & 0x70))
__device__ __forceinline__ void cp16(uint32_t dst, const void* src) {
    asm volatile("cp.async.cg.shared.global [%0], [%1], 16;" :: "r"(dst), "l"(src));
}
#define CP_COMMIT() asm volatile("cp.async.commit_group;" ::: "memory")

#define LDSM_X4(R, A)                                                        \
    asm volatile("ldmatrix.sync.aligned.m8n8.x4.shared.b16 {%0,%1,%2,%3}, [%4];" \
        : "=r"((R)[0]), "=r"((R)[1]), "=r"((R)[2]), "=r"((R)[3]) : "r"(A))

#define MMA_BF16(Dd, Aa, Bb)                                                 \
    asm volatile("mma.sync.aligned.m16n8k16.row.col.f32.bf16.bf16.f32 "      \
        "{%0,%1,%2,%3}, {%4,%5,%6,%7}, {%8,%9}, {%0,%1,%2,%3};"              \
        : "+f"((Dd)[0]), "+f"((Dd)[1]), "+f"((Dd)[2]), "+f"((Dd)[3])         \
        : "r"((Aa)[0]), "r"((Aa)[1]), "r"((Aa)[2]), "r"((Aa)[3]),            \
          "r"((Bb)[0]), "r"((Bb)[1]))

// ---------------------------------------------------------------------------
// Align: warp per (row, source). Binary search -> contiguous slice mean ->
// bf16 hi/lo split write.
// ---------------------------------------------------------------------------
__global__ __launch_bounds__(256) void align_kernel(
    const float* __restrict__ hing, const float* __restrict__ rob,
    const int* __restrict__ hids, const int* __restrict__ rids)
{
    int unit = blockIdx.x * 8 + (threadIdx.x >> 5);
    int lane = threadIdx.x & 31;
    int srci = unit & 1;
    int row  = unit >> 1;
    int b = row >> 8;
    int w = row & (W - 1);

    const int* ids = (srci ? rids : hids) + b * S;
    const float* src = srci ? rob : hing;

    int l = 0, r = S;
    while (l < r) { int m = (l + r) >> 1; if (ids[m] < w) l = m + 1; else r = m; }
    int lo = l;
    r = S;
    while (l < r) { int m = (l + r) >> 1; if (ids[m] <= w) l = m + 1; else r = m; }
    int hi = l;

    float inv = (hi > lo) ? 1.0f / (float)(hi - lo) : 0.0f;
    const float4* base = (const float4*)(src + (size_t)b * S * D);
    __nv_bfloat162* dh = (__nv_bfloat162*)(g_xh + (size_t)row * KX + srci * D);
    __nv_bfloat162* dl = (__nv_bfloat162*)(g_xl + (size_t)row * KX + srci * D);

    const int D4 = D / 4;
    #pragma unroll 1
    for (int d = lane; d < D4; d += 32) {
        float ax = 0.f, ay = 0.f, az = 0.f, aw = 0.f;
        for (int s = lo; s < hi; s++) {
            float4 v = base[(size_t)s * D4 + d];
            ax += v.x; ay += v.y; az += v.z; aw += v.w;
        }
        ax *= inv; ay *= inv; az *= inv; aw *= inv;
        __nv_bfloat16 h0 = __float2bfloat16(ax), h1 = __float2bfloat16(ay);
        __nv_bfloat16 h2 = __float2bfloat16(az), h3 = __float2bfloat16(aw);
        __nv_bfloat16 l0 = __float2bfloat16(ax - __bfloat162float(h0));
        __nv_bfloat16 l1 = __float2bfloat16(ay - __bfloat162float(h1));
        __nv_bfloat16 l2v = __float2bfloat16(az - __bfloat162float(h2));
        __nv_bfloat16 l3 = __float2bfloat16(aw - __bfloat162float(h3));
        __nv_bfloat162 p;
        p.x = h0; p.y = h1; dh[d * 2]     = p;
        p.x = h2; p.y = h3; dh[d * 2 + 1] = p;
        p.x = l0; p.y = l1; dl[d * 2]     = p;
        p.x = l2v; p.y = l3; dl[d * 2 + 1] = p;
    }
}

// W1 prep: transpose [K,H] -> [H,K], split bf16 hi/lo.
__global__ __launch_bounds__(256) void prep_w1(const float* __restrict__ w1)
{
    int idx = blockIdx.x * 256 + threadIdx.x;   // n*KX + k
    int n = idx / KX;
    int k = idx - n * KX;
    float v = w1[(size_t)k * H + n];
    __nv_bfloat16 h = __float2bfloat16(v);
    g_w1h[idx] = h;
    g_w1l[idx] = __float2bfloat16(v - __bfloat162float(h));
}

// ---------------------------------------------------------------------------
// Router: mma.sync bf16-split GEMM (CTA: M=64, N=256, K=1536, 3 combos)
// + fused alpha / blend / head / l2 epilogue.
// ---------------------------------------------------------------------------
__device__ __forceinline__ void load_tiles(uint32_t st, int kk, int r0, int tid)
{
    const __nv_bfloat16* axh = g_xh + (size_t)r0 * KX + kk;
    const __nv_bfloat16* axl = g_xl + (size_t)r0 * KX + kk;
    #pragma unroll
    for (int t = 0; t < 2; t++) {
        int idx = t * 256 + tid;           // 512 chunks: 64 rows x 8
        int r = idx >> 3, c = idx & 7;
        uint32_t sw = SWZ((uint32_t)(r * 128 + c * 16));
        size_t go = (size_t)r * KX + c * 8;
        cp16(st + OFF_AH + sw, axh + go);
        cp16(st + OFF_AL + sw, axl + go);
    }
    const __nv_bfloat16* bh = g_w1h + kk;
    const __nv_bfloat16* bl = g_w1l + kk;
    #pragma unroll
    for (int t = 0; t < 8; t++) {
        int idx = t * 256 + tid;           // 2048 chunks: 256 rows x 8
        int n = idx >> 3, c = idx & 7;
        uint32_t sw = SWZ((uint32_t)(n * 128 + c * 16));
        size_t go = (size_t)n * KX + c * 8;
        cp16(st + OFF_BH + sw, bh + go);
        cp16(st + OFF_BL + sw, bl + go);
    }
}

__global__ __launch_bounds__(256, 1) void router_kernel(
    const float* __restrict__ b1, const float* __restrict__ w2,
    const float* __restrict__ b2p,
    const float* __restrict__ headw, const float* __restrict__ headb,
    float* __restrict__ out)
{
    extern __shared__ char smem[];
    uint32_t sb = smem_u32(smem);
    int tid = threadIdx.x;
    int wid = tid >> 5, lane = tid & 31;
    int warp_m = wid >> 2;        // 0..1  (rows warp_m*32 .. +32)
    int warp_n = wid & 3;         // 0..3  (cols warp_n*64 .. +64)
    int r0 = blockIdx.x * CTA_M;

    float* s_b1    = (float*)(smem);
    float* s_w2    = (float*)(smem + 1024);
    float* s_part  = (float*)(smem + 2048);   // 64 floats
    float* s_alpha = (float*)(smem + 2304);   // 64 floats

    s_b1[tid] = b1[tid];
    s_w2[tid] = w2[tid];
    if (tid < CTA_M) s_part[tid] = 0.0f;
    float b2 = *b2p;
    __syncthreads();

    // prologue: both stages
    load_tiles(sb + OFF_TILES, 0, r0, tid);
    CP_COMMIT();
    load_tiles(sb + OFF_TILES + STAGE_BYTES, KT2, r0, tid);
    CP_COMMIT();

    float acc[2][8][4];
    #pragma unroll
    for (int mi = 0; mi < 2; mi++)
        #pragma unroll
        for (int ni = 0; ni < 8; ni++)
            #pragma unroll
            for (int j = 0; j < 4; j++) acc[mi][ni][j] = 0.0f;

    // per-thread ldmatrix addressing (within tile, pre-swizzle parts)
    int arow  = warp_m * 32 + (lane & 15);
    uint32_t acol = ((uint32_t)(lane >> 4)) * 16;
    int nrow  = warp_n * 64 + (((lane >> 4) & 1) << 3) + (lane & 7);
    uint32_t bcol = (((uint32_t)(lane >> 3)) & 1) << 4;

    for (int it = 0; it < NITER; it++) {
        if (it < NITER - 1)
            asm volatile("cp.async.wait_group 1;" ::: "memory");
        else
            asm volatile("cp.async.wait_group 0;" ::: "memory");
        __syncthreads();

        uint32_t st = sb + OFF_TILES + (uint32_t)(it & 1) * STAGE_BYTES;

        #pragma unroll
        for (int ks = 0; ks < 4; ks++) {
            uint32_t kb = (uint32_t)ks * 32;
            uint32_t ah[2][4], al[2][4];
            #pragma unroll
            for (int mi = 0; mi < 2; mi++) {
                uint32_t off = SWZ((uint32_t)((arow + mi * 16) * 128) + acol + kb);
                LDSM_X4(ah[mi], st + OFF_AH + off);
                LDSM_X4(al[mi], st + OFF_AL + off);
            }
            uint32_t bh[8][2], bl[8][2];
            #pragma unroll
            for (int g = 0; g < 4; g++) {
                uint32_t off = SWZ((uint32_t)((nrow + g * 16) * 128) + bcol + kb);
                uint32_t rh[4], rl[4];
                LDSM_X4(rh, st + OFF_BH + off);
                LDSM_X4(rl, st + OFF_BL + off);
                bh[2 * g][0] = rh[0]; bh[2 * g][1] = rh[1];
                bh[2 * g + 1][0] = rh[2]; bh[2 * g + 1][1] = rh[3];
                bl[2 * g][0] = rl[0]; bl[2 * g][1] = rl[1];
                bl[2 * g + 1][0] = rl[2]; bl[2 * g + 1][1] = rl[3];
            }
            #pragma unroll
            for (int mi = 0; mi < 2; mi++)
                #pragma unroll
                for (int ni = 0; ni < 8; ni++) {
                    MMA_BF16(acc[mi][ni], ah[mi], bh[ni]);   // Ah*Bh
                    MMA_BF16(acc[mi][ni], ah[mi], bl[ni]);   // Ah*Bl
                    MMA_BF16(acc[mi][ni], al[mi], bh[ni]);   // Al*Bh
                }
        }

        __syncthreads();
        if (it + 2 < NITER) {
            load_tiles(st, (it + 2) * KT2, r0, tid);
            CP_COMMIT();
        }
    }

    // alpha partials: relu(hdn + b1) . w2 over this warp's 64 columns
    #pragma unroll
    for (int mi = 0; mi < 2; mi++) {
        #pragma unroll
        for (int rh = 0; rh < 2; rh++) {
            float part = 0.0f;
            #pragma unroll
            for (int ni = 0; ni < 8; ni++) {
                int col0 = warp_n * 64 + ni * 8 + 2 * (lane & 3);
                float h0 = acc[mi][ni][rh * 2 + 0] + s_b1[col0];
                float h1 = acc[mi][ni][rh * 2 + 1] + s_b1[col0 + 1];
                h0 = h0 > 0.f ? h0 : 0.f;
                h1 = h1 > 0.f ? h1 : 0.f;
                part = fmaf(h0, s_w2[col0], part);
                part = fmaf(h1, s_w2[col0 + 1], part);
            }
            part += __shfl_xor_sync(0xffffffffu, part, 1);
            part += __shfl_xor_sync(0xffffffffu, part, 2);
            if ((lane & 3) == 0)
                atomicAdd(&s_part[warp_m * 32 + mi * 16 + rh * 8 + (lane >> 2)], part);
        }
    }
    __syncthreads();
    if (tid < CTA_M) {
        float z = s_part[tid] + b2;
        s_alpha[tid] = 1.0f / (1.0f + expf(-z));
    }
    __syncthreads();

    // blend/head/l2 epilogue: 8 warps x 8 words
    float* out_logits = out;
    float* out_alpha  = out + (size_t)ROWS * L;
    float* out_l2     = out_alpha + ROWS;

    #pragma unroll 1
    for (int wi = 0; wi < 8; wi++) {
        int li = wid * 8 + wi;
        size_t row = (size_t)(r0 + li);
        float al = s_alpha[li];
        float oma = 1.0f - al;
        const __nv_bfloat162* xh2 = (const __nv_bfloat162*)(g_xh + row * KX);
        const __nv_bfloat162* xl2 = (const __nv_bfloat162*)(g_xl + row * KX);

        float lg[L];
        #pragma unroll
        for (int l = 0; l < L; l++) lg[l] = 0.0f;
        float l2 = 0.0f;

        #pragma unroll 1
        for (int d2 = lane; d2 < D / 2; d2 += 32) {
            __nv_bfloat162 hh2 = xh2[d2],         hl2 = xl2[d2];
            __nv_bfloat162 rh2 = xh2[D / 2 + d2], rl2 = xl2[D / 2 + d2];
            float hh[2], hr[2];
            hh[0] = __bfloat162float(hh2.x) + __bfloat162float(hl2.x);
            hh[1] = __bfloat162float(hh2.y) + __bfloat162float(hl2.y);
            hr[0] = __bfloat162float(rh2.x) + __bfloat162float(rl2.x);
            hr[1] = __bfloat162float(rh2.y) + __bfloat162float(rl2.y);
            #pragma unroll
            for (int u = 0; u < 2; u++) {
                int d = d2 * 2 + u;
                float bl = al * hh[u] + oma * hr[u];
                float df = hh[u] - hr[u];
                l2 = fmaf(df, df, l2);
                #pragma unroll
                for (int l = 0; l < L; l++)
                    lg[l] = fmaf(bl, headw[(size_t)d * L + l], lg[l]);
            }
        }
        #pragma unroll
        for (int o = 16; o > 0; o >>= 1) {
            #pragma unroll
            for (int l = 0; l < L; l++)
                lg[l] += __shfl_xor_sync(0xffffffffu, lg[l], o);
            l2 += __shfl_xor_sync(0xffffffffu, l2, o);
        }
        if (lane == 0) {
            #pragma unroll
            for (int l = 0; l < L; l++)
                out_logits[row * L + l] = lg[l] + headb[l];
            out_alpha[row] = al;
            out_l2[row] = sqrtf(l2);
        }
    }
}

extern "C" void kernel_launch(void* const* d_in, const int* in_sizes, int n_in,
                              void* d_out, int out_size)
{
    const float* hing = (const float*)d_in[0];
    const float* rob  = (const float*)d_in[1];
    const int*   hids = (const int*)d_in[2];
    const int*   rids = (const int*)d_in[3];
    // d_in[4] = num_words (unused by the reference outputs)
    const float* w1 = (const float*)d_in[5];
    const float* b1 = (const float*)d_in[6];
    const float* w2 = (const float*)d_in[7];
    const float* b2 = (const float*)d_in[8];
    const float* hw = (const float*)d_in[9];
    const float* hb = (const float*)d_in[10];
    float* out = (float*)d_out;

    cudaFuncSetAttribute(router_kernel,
                         cudaFuncAttributeMaxDynamicSharedMemorySize, SMEM_TOTAL);

    prep_w1<<<(KX * H) / 256, 256>>>(w1);
    align_kernel<<<(ROWS * 2) / 8, 256>>>(hing, rob, hids, rids);
    router_kernel<<<ROWS / CTA_M, 256, SMEM_TOTAL>>>(b1, w2, b2, hw, hb, out);
}

// round 5
// speedup vs baseline: 2.8290x; 1.2064x over previous
#include <cuda_runtime.h>
#include <cuda_fp16.h>
#include <math.h>
#include <stdint.h>

#define BATCH 64
#define S 512
#define D 768
#define W 256
#define KX 1536     // 2*D router input
#define H 256       // router hidden (= GEMM N)
#define L 7
#define ROWS (BATCH * W)   // 16384
#define CTA_M 64
#define KT2 64             // K-tile (fp16 elems) = 128 bytes = one SW128 row
#define NITER (KX / KT2)   // 24

// stage layout (bytes): Ah 8K | Al 8K | B 32K
#define OFF_AH 0u
#define OFF_AL 8192u
#define OFF_B  16384u
#define STAGE_BYTES 49152u
#define OFF_TILES 4096u
#define SMEM_TOTAL (OFF_TILES + 2 * STAGE_BYTES)   // 102400

// fp16 operands: A split hi/lo, W1 rounded once
__device__ __align__(16) __half g_xh[(size_t)ROWS * KX];
__device__ __align__(16) __half g_xl[(size_t)ROWS * KX];
__device__ __align__(16) __half g_w1[(size_t)H * KX];   // [n][k]

__device__ __forceinline__ uint32_t smem_u32(const void* p) {
    uint32_t a;
    asm("{ .reg .u64 t; cvta.to.shared.u64 t, %1; cvt.u32.u64 %0, t; }"
        : "=r"(a) : "l"(p));
    return a;
}
#define SWZ(x) ((x) ^ (((x) >> 3) & 0x70))
__device__ __forceinline__ void cp16(uint32_t dst, const void* src) {
    asm volatile("cp.async.cg.shared.global [%0], [%1], 16;" :: "r"(dst), "l"(src));
}
#define CP_COMMIT() asm volatile("cp.async.commit_group;" ::: "memory")

#define LDSM_X4(R, A)                                                        \
    asm volatile("ldmatrix.sync.aligned.m8n8.x4.shared.b16 {%0,%1,%2,%3}, [%4];" \
        : "=r"((R)[0]), "=r"((R)[1]), "=r"((R)[2]), "=r"((R)[3]) : "r"(A))

#define MMA_F16(Dd, Aa, Bb)                                                  \
    asm volatile("mma.sync.aligned.m16n8k16.row.col.f32.f16.f16.f32 "        \
        "{%0,%1,%2,%3}, {%4,%5,%6,%7}, {%8,%9}, {%0,%1,%2,%3};"              \
        : "+f"((Dd)[0]), "+f"((Dd)[1]), "+f"((Dd)[2]), "+f"((Dd)[3])         \
        : "r"((Aa)[0]), "r"((Aa)[1]), "r"((Aa)[2]), "r"((Aa)[3]),            \
          "r"((Bb)[0]), "r"((Bb)[1]))

// ---------------------------------------------------------------------------
// Align: warp per (row, source). Binary search -> contiguous slice mean ->
// fp16 hi/lo split write.
// ---------------------------------------------------------------------------
__global__ __launch_bounds__(256) void align_kernel(
    const float* __restrict__ hing, const float* __restrict__ rob,
    const int* __restrict__ hids, const int* __restrict__ rids)
{
    int unit = blockIdx.x * 8 + (threadIdx.x >> 5);
    int lane = threadIdx.x & 31;
    int srci = unit & 1;
    int row  = unit >> 1;
    int b = row >> 8;
    int w = row & (W - 1);

    const int* ids = (srci ? rids : hids) + b * S;
    const float* src = srci ? rob : hing;

    int l = 0, r = S;
    while (l < r) { int m = (l + r) >> 1; if (ids[m] < w) l = m + 1; else r = m; }
    int lo = l;
    r = S;
    while (l < r) { int m = (l + r) >> 1; if (ids[m] <= w) l = m + 1; else r = m; }
    int hi = l;

    float inv = (hi > lo) ? 1.0f / (float)(hi - lo) : 0.0f;
    const float4* base = (const float4*)(src + (size_t)b * S * D);
    __half2* dh = (__half2*)(g_xh + (size_t)row * KX + srci * D);
    __half2* dl = (__half2*)(g_xl + (size_t)row * KX + srci * D);

    const int D4 = D / 4;
    #pragma unroll 1
    for (int d = lane; d < D4; d += 32) {
        float ax = 0.f, ay = 0.f, az = 0.f, aw = 0.f;
        for (int s = lo; s < hi; s++) {
            float4 v = base[(size_t)s * D4 + d];
            ax += v.x; ay += v.y; az += v.z; aw += v.w;
        }
        ax *= inv; ay *= inv; az *= inv; aw *= inv;
        __half h0 = __float2half_rn(ax), h1 = __float2half_rn(ay);
        __half h2 = __float2half_rn(az), h3 = __float2half_rn(aw);
        __half l0 = __float2half_rn(ax - __half2float(h0));
        __half l1 = __float2half_rn(ay - __half2float(h1));
        __half l2v = __float2half_rn(az - __half2float(h2));
        __half l3 = __float2half_rn(aw - __half2float(h3));
        __half2 p;
        p.x = h0; p.y = h1; dh[d * 2]     = p;
        p.x = h2; p.y = h3; dh[d * 2 + 1] = p;
        p.x = l0; p.y = l1; dl[d * 2]     = p;
        p.x = l2v; p.y = l3; dl[d * 2 + 1] = p;
    }
}

// W1 prep: transpose [K,H] -> [H,K], round to fp16.
__global__ __launch_bounds__(256) void prep_w1(const float* __restrict__ w1)
{
    int idx = blockIdx.x * 256 + threadIdx.x;   // n*KX + k
    int n = idx / KX;
    int k = idx - n * KX;
    g_w1[idx] = __float2half_rn(w1[(size_t)k * H + n]);
}

// ---------------------------------------------------------------------------
// Router: mma.sync fp16 A-split GEMM (CTA: M=64, N=256, K=1536, 2 passes)
// + fused alpha / blend / head / l2 epilogue.
// ---------------------------------------------------------------------------
__device__ __forceinline__ void load_tiles(uint32_t st, int kk, int r0, int tid)
{
    const __half* axh = g_xh + (size_t)r0 * KX + kk;
    const __half* axl = g_xl + (size_t)r0 * KX + kk;
    #pragma unroll
    for (int t = 0; t < 2; t++) {
        int idx = t * 256 + tid;           // 512 chunks: 64 rows x 8
        int r = idx >> 3, c = idx & 7;
        uint32_t sw = SWZ((uint32_t)(r * 128 + c * 16));
        size_t go = (size_t)r * KX + c * 8;
        cp16(st + OFF_AH + sw, axh + go);
        cp16(st + OFF_AL + sw, axl + go);
    }
    const __half* bw = g_w1 + kk;
    #pragma unroll
    for (int t = 0; t < 8; t++) {
        int idx = t * 256 + tid;           // 2048 chunks: 256 rows x 8
        int n = idx >> 3, c = idx & 7;
        uint32_t sw = SWZ((uint32_t)(n * 128 + c * 16));
        cp16(st + OFF_B + sw, bw + (size_t)n * KX + c * 8);
    }
}

__global__ __launch_bounds__(256, 2) void router_kernel(
    const float* __restrict__ b1, const float* __restrict__ w2,
    const float* __restrict__ b2p,
    const float* __restrict__ headw, const float* __restrict__ headb,
    float* __restrict__ out)
{
    extern __shared__ char smem[];
    uint32_t sb = smem_u32(smem);
    int tid = threadIdx.x;
    int wid = tid >> 5, lane = tid & 31;
    int warp_m = wid >> 2;        // 0..1  (rows warp_m*32 .. +32)
    int warp_n = wid & 3;         // 0..3  (cols warp_n*64 .. +64)
    int r0 = blockIdx.x * CTA_M;

    float* s_b1    = (float*)(smem);
    float* s_w2    = (float*)(smem + 1024);
    float* s_part  = (float*)(smem + 2048);   // 64 floats
    float* s_alpha = (float*)(smem + 2304);   // 64 floats

    s_b1[tid] = b1[tid];
    s_w2[tid] = w2[tid];
    if (tid < CTA_M) s_part[tid] = 0.0f;
    float b2 = *b2p;
    __syncthreads();

    // prologue: both stages
    load_tiles(sb + OFF_TILES, 0, r0, tid);
    CP_COMMIT();
    load_tiles(sb + OFF_TILES + STAGE_BYTES, KT2, r0, tid);
    CP_COMMIT();

    float acc[2][8][4];
    #pragma unroll
    for (int mi = 0; mi < 2; mi++)
        #pragma unroll
        for (int ni = 0; ni < 8; ni++)
            #pragma unroll
            for (int j = 0; j < 4; j++) acc[mi][ni][j] = 0.0f;

    // per-thread ldmatrix addressing (within tile, pre-swizzle parts)
    int arow  = warp_m * 32 + (lane & 15);
    uint32_t acol = ((uint32_t)(lane >> 4)) * 16;
    int nrow  = warp_n * 64 + (((lane >> 4) & 1) << 3) + (lane & 7);
    uint32_t bcol = (((uint32_t)(lane >> 3)) & 1) << 4;

    for (int it = 0; it < NITER; it++) {
        if (it < NITER - 1)
            asm volatile("cp.async.wait_group 1;" ::: "memory");
        else
            asm volatile("cp.async.wait_group 0;" ::: "memory");
        __syncthreads();

        uint32_t st = sb + OFF_TILES + (uint32_t)(it & 1) * STAGE_BYTES;

        #pragma unroll
        for (int ks = 0; ks < 4; ks++) {
            uint32_t kb = (uint32_t)ks * 32;
            uint32_t ah[2][4], al[2][4];
            #pragma unroll
            for (int mi = 0; mi < 2; mi++) {
                uint32_t off = SWZ((uint32_t)((arow + mi * 16) * 128) + acol + kb);
                LDSM_X4(ah[mi], st + OFF_AH + off);
                LDSM_X4(al[mi], st + OFF_AL + off);
            }
            uint32_t bb[8][2];
            #pragma unroll
            for (int g = 0; g < 4; g++) {
                uint32_t off = SWZ((uint32_t)((nrow + g * 16) * 128) + bcol + kb);
                uint32_t rb[4];
                LDSM_X4(rb, st + OFF_B + off);
                bb[2 * g][0] = rb[0]; bb[2 * g][1] = rb[1];
                bb[2 * g + 1][0] = rb[2]; bb[2 * g + 1][1] = rb[3];
            }
            #pragma unroll
            for (int mi = 0; mi < 2; mi++)
                #pragma unroll
                for (int ni = 0; ni < 8; ni++) {
                    MMA_F16(acc[mi][ni], ah[mi], bb[ni]);   // Ah*B
                    MMA_F16(acc[mi][ni], al[mi], bb[ni]);   // Al*B
                }
        }

        __syncthreads();
        if (it + 2 < NITER) {
            load_tiles(st, (it + 2) * KT2, r0, tid);
            CP_COMMIT();
        }
    }

    // alpha partials: relu(hdn + b1) . w2 over this warp's 64 columns
    #pragma unroll
    for (int mi = 0; mi < 2; mi++) {
        #pragma unroll
        for (int rh = 0; rh < 2; rh++) {
            float part = 0.0f;
            #pragma unroll
            for (int ni = 0; ni < 8; ni++) {
                int col0 = warp_n * 64 + ni * 8 + 2 * (lane & 3);
                float h0 = acc[mi][ni][rh * 2 + 0] + s_b1[col0];
                float h1 = acc[mi][ni][rh * 2 + 1] + s_b1[col0 + 1];
                h0 = h0 > 0.f ? h0 : 0.f;
                h1 = h1 > 0.f ? h1 : 0.f;
                part = fmaf(h0, s_w2[col0], part);
                part = fmaf(h1, s_w2[col0 + 1], part);
            }
            part += __shfl_xor_sync(0xffffffffu, part, 1);
            part += __shfl_xor_sync(0xffffffffu, part, 2);
            if ((lane & 3) == 0)
                atomicAdd(&s_part[warp_m * 32 + mi * 16 + rh * 8 + (lane >> 2)], part);
        }
    }
    __syncthreads();
    if (tid < CTA_M) {
        float z = s_part[tid] + b2;
        s_alpha[tid] = 1.0f / (1.0f + expf(-z));
    }
    __syncthreads();

    // blend/head/l2 epilogue: 8 warps x 8 words
    float* out_logits = out;
    float* out_alpha  = out + (size_t)ROWS * L;
    float* out_l2     = out_alpha + ROWS;

    #pragma unroll 1
    for (int wi = 0; wi < 8; wi++) {
        int li = wid * 8 + wi;
        size_t row = (size_t)(r0 + li);
        float al = s_alpha[li];
        float oma = 1.0f - al;
        const __half2* xh2 = (const __half2*)(g_xh + row * KX);
        const __half2* xl2 = (const __half2*)(g_xl + row * KX);

        float lg[L];
        #pragma unroll
        for (int l = 0; l < L; l++) lg[l] = 0.0f;
        float l2 = 0.0f;

        #pragma unroll 1
        for (int d2 = lane; d2 < D / 2; d2 += 32) {
            __half2 hh2 = xh2[d2],         hl2 = xl2[d2];
            __half2 rh2 = xh2[D / 2 + d2], rl2 = xl2[D / 2 + d2];
            float hh[2], hr[2];
            hh[0] = __half2float(hh2.x) + __half2float(hl2.x);
            hh[1] = __half2float(hh2.y) + __half2float(hl2.y);
            hr[0] = __half2float(rh2.x) + __half2float(rl2.x);
            hr[1] = __half2float(rh2.y) + __half2float(rl2.y);
            #pragma unroll
            for (int u = 0; u < 2; u++) {
                int d = d2 * 2 + u;
                float bl = al * hh[u] + oma * hr[u];
                float df = hh[u] - hr[u];
                l2 = fmaf(df, df, l2);
                #pragma unroll
                for (int l = 0; l < L; l++)
                    lg[l] = fmaf(bl, headw[(size_t)d * L + l], lg[l]);
            }
        }
        #pragma unroll
        for (int o = 16; o > 0; o >>= 1) {
            #pragma unroll
            for (int l = 0; l < L; l++)
                lg[l] += __shfl_xor_sync(0xffffffffu, lg[l], o);
            l2 += __shfl_xor_sync(0xffffffffu, l2, o);
        }
        if (lane == 0) {
            #pragma unroll
            for (int l = 0; l < L; l++)
                out_logits[row * L + l] = lg[l] + headb[l];
            out_alpha[row] = al;
            out_l2[row] = sqrtf(l2);
        }
    }
}

extern "C" void kernel_launch(void* const* d_in, const int* in_sizes, int n_in,
                              void* d_out, int out_size)
{
    const float* hing = (const float*)d_in[0];
    const float* rob  = (const float*)d_in[1];
    const int*   hids = (const int*)d_in[2];
    const int*   rids = (const int*)d_in[3];
    // d_in[4] = num_words (unused by the reference outputs)
    const float* w1 = (const float*)d_in[5];
    const float* b1 = (const float*)d_in[6];
    const float* w2 = (const float*)d_in[7];
    const float* b2 = (const float*)d_in[8];
    const float* hw = (const float*)d_in[9];
    const float* hb = (const float*)d_in[10];
    float* out = (float*)d_out;

    cudaFuncSetAttribute(router_kernel,
                         cudaFuncAttributeMaxDynamicSharedMemorySize, SMEM_TOTAL);

    prep_w1<<<(KX * H) / 256, 256>>>(w1);
    align_kernel<<<(ROWS * 2) / 8, 256>>>(hing, rob, hids, rids);
    router_kernel<<<ROWS / CTA_M, 256, SMEM_TOTAL>>>(b1, w2, b2, hw, hb, out);
}

// round 6
// speedup vs baseline: 3.5528x; 1.2558x over previous
#include <cuda_runtime.h>
#include <cuda_fp16.h>
#include <math.h>
#include <stdint.h>

#define BATCH 64
#define S 512
#define D 768
#define W 256
#define KX 1536     // 2*D router input
#define H 256       // router hidden (= GEMM N)
#define L 7
#define ROWS (BATCH * W)   // 16384
#define CTA_M 64
#define KT2 64             // K-tile (fp16 elems) = 128 bytes = one SW128 row
#define NITER (KX / KT2)   // 24

// stage layout (bytes): A 8K | B 32K
#define OFF_A 0u
#define OFF_B 8192u
#define STAGE_BYTES 40960u
#define OFF_TILES 4096u
#define SMEM_TOTAL (OFF_TILES + 2 * STAGE_BYTES)   // 86016

// fp16 operands (single rounding)
__device__ __align__(16) __half g_xh[(size_t)ROWS * KX];
__device__ __align__(16) __half g_w1[(size_t)H * KX];   // [n][k]

__device__ __forceinline__ uint32_t smem_u32(const void* p) {
    uint32_t a;
    asm("{ .reg .u64 t; cvta.to.shared.u64 t, %1; cvt.u32.u64 %0, t; }"
        : "=r"(a) : "l"(p));
    return a;
}
#define SWZ(x) ((x) ^ (((x) >> 3) & 0x70))
__device__ __forceinline__ void cp16(uint32_t dst, const void* src) {
    asm volatile("cp.async.cg.shared.global [%0], [%1], 16;" :: "r"(dst), "l"(src));
}
#define CP_COMMIT() asm volatile("cp.async.commit_group;" ::: "memory")

#define LDSM_X4(R, A)                                                        \
    asm volatile("ldmatrix.sync.aligned.m8n8.x4.shared.b16 {%0,%1,%2,%3}, [%4];" \
        : "=r"((R)[0]), "=r"((R)[1]), "=r"((R)[2]), "=r"((R)[3]) : "r"(A))

#define MMA_F16(Dd, Aa, Bb)                                                  \
    asm volatile("mma.sync.aligned.m16n8k16.row.col.f32.f16.f16.f32 "        \
        "{%0,%1,%2,%3}, {%4,%5,%6,%7}, {%8,%9}, {%0,%1,%2,%3};"              \
        : "+f"((Dd)[0]), "+f"((Dd)[1]), "+f"((Dd)[2]), "+f"((Dd)[3])         \
        : "r"((Aa)[0]), "r"((Aa)[1]), "r"((Aa)[2]), "r"((Aa)[3]),            \
          "r"((Bb)[0]), "r"((Bb)[1]))

// ---------------------------------------------------------------------------
// Align: warp per (row, source). Binary search -> contiguous slice mean ->
// fp16 write.
// ---------------------------------------------------------------------------
__global__ __launch_bounds__(256) void align_kernel(
    const float* __restrict__ hing, const float* __restrict__ rob,
    const int* __restrict__ hids, const int* __restrict__ rids)
{
    int unit = blockIdx.x * 8 + (threadIdx.x >> 5);
    int lane = threadIdx.x & 31;
    int srci = unit & 1;
    int row  = unit >> 1;
    int b = row >> 8;
    int w = row & (W - 1);

    const int* ids = (srci ? rids : hids) + b * S;
    const float* src = srci ? rob : hing;

    int l = 0, r = S;
    while (l < r) { int m = (l + r) >> 1; if (ids[m] < w) l = m + 1; else r = m; }
    int lo = l;
    r = S;
    while (l < r) { int m = (l + r) >> 1; if (ids[m] <= w) l = m + 1; else r = m; }
    int hi = l;

    float inv = (hi > lo) ? 1.0f / (float)(hi - lo) : 0.0f;
    const float4* base = (const float4*)(src + (size_t)b * S * D);
    __half2* dh = (__half2*)(g_xh + (size_t)row * KX + srci * D);

    const int D4 = D / 4;
    #pragma unroll 1
    for (int d = lane; d < D4; d += 32) {
        float ax = 0.f, ay = 0.f, az = 0.f, aw = 0.f;
        for (int s = lo; s < hi; s++) {
            float4 v = base[(size_t)s * D4 + d];
            ax += v.x; ay += v.y; az += v.z; aw += v.w;
        }
        ax *= inv; ay *= inv; az *= inv; aw *= inv;
        __half2 p0, p1;
        p0.x = __float2half_rn(ax); p0.y = __float2half_rn(ay);
        p1.x = __float2half_rn(az); p1.y = __float2half_rn(aw);
        dh[d * 2]     = p0;
        dh[d * 2 + 1] = p1;
    }
}

// W1 prep: transpose [K,H] -> [H,K], round to fp16.
__global__ __launch_bounds__(256) void prep_w1(const float* __restrict__ w1)
{
    int idx = blockIdx.x * 256 + threadIdx.x;   // n*KX + k
    int n = idx / KX;
    int k = idx - n * KX;
    g_w1[idx] = __float2half_rn(w1[(size_t)k * H + n]);
}

// ---------------------------------------------------------------------------
// Router: mma.sync fp16 GEMM (CTA: M=64, N=256, K=1536, single pass)
// + fused alpha / blend / head / l2 epilogue.
// ---------------------------------------------------------------------------
__device__ __forceinline__ void load_tiles(uint32_t st, int kk, int r0, int tid)
{
    const __half* ax = g_xh + (size_t)r0 * KX + kk;
    #pragma unroll
    for (int t = 0; t < 2; t++) {
        int idx = t * 256 + tid;           // 512 chunks: 64 rows x 8
        int r = idx >> 3, c = idx & 7;
        uint32_t sw = SWZ((uint32_t)(r * 128 + c * 16));
        cp16(st + OFF_A + sw, ax + (size_t)r * KX + c * 8);
    }
    const __half* bw = g_w1 + kk;
    #pragma unroll
    for (int t = 0; t < 8; t++) {
        int idx = t * 256 + tid;           // 2048 chunks: 256 rows x 8
        int n = idx >> 3, c = idx & 7;
        uint32_t sw = SWZ((uint32_t)(n * 128 + c * 16));
        cp16(st + OFF_B + sw, bw + (size_t)n * KX + c * 8);
    }
}

__global__ __launch_bounds__(256, 2) void router_kernel(
    const float* __restrict__ b1, const float* __restrict__ w2,
    const float* __restrict__ b2p,
    const float* __restrict__ headw, const float* __restrict__ headb,
    float* __restrict__ out)
{
    extern __shared__ char smem[];
    uint32_t sb = smem_u32(smem);
    int tid = threadIdx.x;
    int wid = tid >> 5, lane = tid & 31;
    int warp_m = wid >> 2;        // 0..1  (rows warp_m*32 .. +32)
    int warp_n = wid & 3;         // 0..3  (cols warp_n*64 .. +64)
    int r0 = blockIdx.x * CTA_M;

    float* s_b1    = (float*)(smem);
    float* s_w2    = (float*)(smem + 1024);
    float* s_part  = (float*)(smem + 2048);   // 64 floats
    float* s_alpha = (float*)(smem + 2304);   // 64 floats

    s_b1[tid] = b1[tid];
    s_w2[tid] = w2[tid];
    if (tid < CTA_M) s_part[tid] = 0.0f;
    float b2 = *b2p;
    __syncthreads();

    // prologue: both stages
    load_tiles(sb + OFF_TILES, 0, r0, tid);
    CP_COMMIT();
    load_tiles(sb + OFF_TILES + STAGE_BYTES, KT2, r0, tid);
    CP_COMMIT();

    float acc[2][8][4];
    #pragma unroll
    for (int mi = 0; mi < 2; mi++)
        #pragma unroll
        for (int ni = 0; ni < 8; ni++)
            #pragma unroll
            for (int j = 0; j < 4; j++) acc[mi][ni][j] = 0.0f;

    // per-thread ldmatrix addressing (within tile, pre-swizzle parts)
    int arow  = warp_m * 32 + (lane & 15);
    uint32_t acol = ((uint32_t)(lane >> 4)) * 16;
    int nrow  = warp_n * 64 + (((lane >> 4) & 1) << 3) + (lane & 7);
    uint32_t bcol = (((uint32_t)(lane >> 3)) & 1) << 4;

    for (int it = 0; it < NITER; it++) {
        if (it < NITER - 1)
            asm volatile("cp.async.wait_group 1;" ::: "memory");
        else
            asm volatile("cp.async.wait_group 0;" ::: "memory");
        __syncthreads();

        uint32_t st = sb + OFF_TILES + (uint32_t)(it & 1) * STAGE_BYTES;

        #pragma unroll
        for (int ks = 0; ks < 4; ks++) {
            uint32_t kb = (uint32_t)ks * 32;
            uint32_t aa[2][4];
            #pragma unroll
            for (int mi = 0; mi < 2; mi++) {
                uint32_t off = SWZ((uint32_t)((arow + mi * 16) * 128) + acol + kb);
                LDSM_X4(aa[mi], st + OFF_A + off);
            }
            uint32_t bb[8][2];
            #pragma unroll
            for (int g = 0; g < 4; g++) {
                uint32_t off = SWZ((uint32_t)((nrow + g * 16) * 128) + bcol + kb);
                uint32_t rb[4];
                LDSM_X4(rb, st + OFF_B + off);
                bb[2 * g][0] = rb[0]; bb[2 * g][1] = rb[1];
                bb[2 * g + 1][0] = rb[2]; bb[2 * g + 1][1] = rb[3];
            }
            #pragma unroll
            for (int mi = 0; mi < 2; mi++)
                #pragma unroll
                for (int ni = 0; ni < 8; ni++)
                    MMA_F16(acc[mi][ni], aa[mi], bb[ni]);
        }

        __syncthreads();
        if (it + 2 < NITER) {
            load_tiles(st, (it + 2) * KT2, r0, tid);
            CP_COMMIT();
        }
    }

    // alpha partials: relu(hdn + b1) . w2 over this warp's 64 columns
    #pragma unroll
    for (int mi = 0; mi < 2; mi++) {
        #pragma unroll
        for (int rh = 0; rh < 2; rh++) {
            float part = 0.0f;
            #pragma unroll
            for (int ni = 0; ni < 8; ni++) {
                int col0 = warp_n * 64 + ni * 8 + 2 * (lane & 3);
                float h0 = acc[mi][ni][rh * 2 + 0] + s_b1[col0];
                float h1 = acc[mi][ni][rh * 2 + 1] + s_b1[col0 + 1];
                h0 = h0 > 0.f ? h0 : 0.f;
                h1 = h1 > 0.f ? h1 : 0.f;
                part = fmaf(h0, s_w2[col0], part);
                part = fmaf(h1, s_w2[col0 + 1], part);
            }
            part += __shfl_xor_sync(0xffffffffu, part, 1);
            part += __shfl_xor_sync(0xffffffffu, part, 2);
            if ((lane & 3) == 0)
                atomicAdd(&s_part[warp_m * 32 + mi * 16 + rh * 8 + (lane >> 2)], part);
        }
    }
    __syncthreads();
    if (tid < CTA_M) {
        float z = s_part[tid] + b2;
        s_alpha[tid] = 1.0f / (1.0f + expf(-z));
    }
    __syncthreads();

    // blend/head/l2 epilogue: 8 warps x 8 words
    float* out_logits = out;
    float* out_alpha  = out + (size_t)ROWS * L;
    float* out_l2     = out_alpha + ROWS;

    #pragma unroll 1
    for (int wi = 0; wi < 8; wi++) {
        int li = wid * 8 + wi;
        size_t row = (size_t)(r0 + li);
        float al = s_alpha[li];
        float oma = 1.0f - al;
        const __half2* xh2 = (const __half2*)(g_xh + row * KX);

        float lg[L];
        #pragma unroll
        for (int l = 0; l < L; l++) lg[l] = 0.0f;
        float l2 = 0.0f;

        #pragma unroll 1
        for (int d2 = lane; d2 < D / 2; d2 += 32) {
            __half2 hh2 = xh2[d2];
            __half2 rr2 = xh2[D / 2 + d2];
            float hh[2], hr[2];
            hh[0] = __half2float(hh2.x); hh[1] = __half2float(hh2.y);
            hr[0] = __half2float(rr2.x); hr[1] = __half2float(rr2.y);
            #pragma unroll
            for (int u = 0; u < 2; u++) {
                int d = d2 * 2 + u;
                float bl = al * hh[u] + oma * hr[u];
                float df = hh[u] - hr[u];
                l2 = fmaf(df, df, l2);
                #pragma unroll
                for (int l = 0; l < L; l++)
                    lg[l] = fmaf(bl, headw[(size_t)d * L + l], lg[l]);
            }
        }
        #pragma unroll
        for (int o = 16; o > 0; o >>= 1) {
            #pragma unroll
            for (int l = 0; l < L; l++)
                lg[l] += __shfl_xor_sync(0xffffffffu, lg[l], o);
            l2 += __shfl_xor_sync(0xffffffffu, l2, o);
        }
        if (lane == 0) {
            #pragma unroll
            for (int l = 0; l < L; l++)
                out_logits[row * L + l] = lg[l] + headb[l];
            out_alpha[row] = al;
            out_l2[row] = sqrtf(l2);
        }
    }
}

extern "C" void kernel_launch(void* const* d_in, const int* in_sizes, int n_in,
                              void* d_out, int out_size)
{
    const float* hing = (const float*)d_in[0];
    const float* rob  = (const float*)d_in[1];
    const int*   hids = (const int*)d_in[2];
    const int*   rids = (const int*)d_in[3];
    // d_in[4] = num_words (unused by the reference outputs)
    const float* w1 = (const float*)d_in[5];
    const float* b1 = (const float*)d_in[6];
    const float* w2 = (const float*)d_in[7];
    const float* b2 = (const float*)d_in[8];
    const float* hw = (const float*)d_in[9];
    const float* hb = (const float*)d_in[10];
    float* out = (float*)d_out;

    cudaFuncSetAttribute(router_kernel,
                         cudaFuncAttributeMaxDynamicSharedMemorySize, SMEM_TOTAL);

    prep_w1<<<(KX * H) / 256, 256>>>(w1);
    align_kernel<<<(ROWS * 2) / 8, 256>>>(hing, rob, hids, rids);
    router_kernel<<<ROWS / CTA_M, 256, SMEM_TOTAL>>>(b1, w2, b2, hw, hb, out);
}